// round 6
// baseline (speedup 1.0000x reference)
#include <cuda_runtime.h>

// Tree DP on deterministic 4-ary heap: L=4096, B=64, C=2.
// msg[b,cs,k] = lse_{cj}( E[b,cj,j] + msg[b,cj,j] + T[k,j,cs,cj] ), j=(k-1)>>2.
//
// Warp-autonomous version: each WARP owns (subtree r in [21,85), batch b).
// No shared memory, no __syncthreads. Parent values propagate via shfl.
// All lanes redundantly compute the root->r path (broadcast loads, identical
// values). Grid: 64 subtrees x 8 batch-groups, 8 warps (=8 batches) / block,
// so warps in a block share r and T lines dedup in L1.

#define LN  4096
#define BN  64
#define CLN 8192

__device__ __forceinline__ float lse2(float a, float b) {
    float mx = fmaxf(a, b);
    float mn = fminf(a, b);
    return mx + __logf(1.0f + __expf(mn - mx));
}

__global__ void __launch_bounds__(256, 1)
k_all(const float* __restrict__ E, const float* __restrict__ T, float* __restrict__ M)
{
    const int lane = threadIdx.x & 31;
    const int w    = threadIdx.x >> 5;
    const int r    = 21 + blockIdx.x;            // subtree root, [21,85)
    const int b    = blockIdx.y * 8 + w;         // this warp's batch

    const int p2 = (r - 1) >> 2;
    const int p1 = (p2 - 1) >> 2;

    const float4* __restrict__ T4 = (const float4*)T;
    const float*  __restrict__ Eb = E + b * CLN;

    // ---------------- prefetch everything (static indices, max MLP) ---------
    // path edges (broadcast across lanes)
    float4 tA = __ldg(T4 + p1 * LN + 0);
    float4 tB = __ldg(T4 + p2 * LN + p1);
    float4 tC = __ldg(T4 + r  * LN + p2);
    float eR0 = Eb[0],  eR1 = Eb[LN];
    float e10 = Eb[p1], e11 = Eb[LN + p1];
    float e20 = Eb[p2], e21 = Eb[LN + p2];
    float er0 = Eb[r],  er1 = Eb[LN + r];

    // level 3: node n3 = lane&3 (lanes 4.. hold duplicates; shfl sources are 0-3)
    const int n3 = lane & 3;
    const int k3 = 4 * r + 1 + n3;
    float4 t3 = __ldg(T4 + k3 * LN + r);
    float e30 = Eb[k3], e31 = Eb[LN + k3];

    // level 4: node n4 = lane&15 (lanes 16.. duplicates; sources are 0-15)
    const int n4 = lane & 15;
    const int k4 = 16 * r + 5 + n4;
    float4 t4 = __ldg(T4 + k4 * LN + ((k4 - 1) >> 2));
    float e40 = Eb[k4], e41 = Eb[LN + k4];

    // level 5 (leaves, no E needed): nodes lane and lane+32
    const int k5a = 64 * r + 21 + lane;
    const int k5b = k5a + 32;
    const bool va = (k5a < LN), vb = (k5b < LN);
    float4 t5a, t5b;
    if (va) t5a = __ldg(T4 + k5a * LN + ((k5a - 1) >> 2));
    if (vb) t5b = __ldg(T4 + k5b * LN + ((k5b - 1) >> 2));

    // node 0 never receives a message -> zero (output poisoned). One writer
    // per (b, c): blockIdx.x == 0 only.
    if (blockIdx.x == 0 && lane < 2)
        M[b * CLN + lane * LN] = 0.0f;

    // ---------------- path root -> p1 -> p2 -> r (all lanes, redundant) -----
    float m0 = lse2(eR0 + tA.x, eR1 + tA.y);
    float m1 = lse2(eR0 + tA.z, eR1 + tA.w);
    if (lane == 0) { M[b * CLN + p1] = m0;  M[b * CLN + LN + p1] = m1; }
    float l0 = e10 + m0, l1 = e11 + m1;

    m0 = lse2(l0 + tB.x, l1 + tB.y);
    m1 = lse2(l0 + tB.z, l1 + tB.w);
    if (lane == 0) { M[b * CLN + p2] = m0;  M[b * CLN + LN + p2] = m1; }
    l0 = e20 + m0;  l1 = e21 + m1;

    m0 = lse2(l0 + tC.x, l1 + tC.y);
    m1 = lse2(l0 + tC.z, l1 + tC.w);
    if (lane == 0) { M[b * CLN + r] = m0;   M[b * CLN + LN + r] = m1; }
    const float lr0 = er0 + m0, lr1 = er1 + m1;     // local(r), in every lane

    // ---------------- level 3 (4 nodes) -------------------------------------
    float m30 = lse2(lr0 + t3.x, lr1 + t3.y);
    float m31 = lse2(lr0 + t3.z, lr1 + t3.w);
    if (lane < 4) { M[b * CLN + k3] = m30;  M[b * CLN + LN + k3] = m31; }
    float l30 = e30 + m30, l31 = e31 + m31;         // lane n holds node n&3

    // ---------------- level 4 (16 nodes) ------------------------------------
    float p40 = __shfl_sync(0xffffffffu, l30, n4 >> 2);
    float p41 = __shfl_sync(0xffffffffu, l31, n4 >> 2);
    float m40 = lse2(p40 + t4.x, p41 + t4.y);
    float m41 = lse2(p40 + t4.z, p41 + t4.w);
    if (lane < 16) { M[b * CLN + k4] = m40;  M[b * CLN + LN + k4] = m41; }
    float l40 = e40 + m40, l41 = e41 + m41;         // lane n holds node n&15

    // ---------------- level 5 (up to 64 leaves) ------------------------------
    float a0 = __shfl_sync(0xffffffffu, l40, lane >> 2);          // parent 0..7
    float a1 = __shfl_sync(0xffffffffu, l41, lane >> 2);
    float c0 = __shfl_sync(0xffffffffu, l40, 8 + (lane >> 2));    // parent 8..15
    float c1 = __shfl_sync(0xffffffffu, l41, 8 + (lane >> 2));
    if (va) {
        float x0 = lse2(a0 + t5a.x, a1 + t5a.y);
        float x1 = lse2(a0 + t5a.z, a1 + t5a.w);
        M[b * CLN + k5a] = x0;  M[b * CLN + LN + k5a] = x1;       // coalesced
    }
    if (vb) {
        float y0 = lse2(c0 + t5b.x, c1 + t5b.y);
        float y1 = lse2(c0 + t5b.z, c1 + t5b.w);
        M[b * CLN + k5b] = y0;  M[b * CLN + LN + k5b] = y1;
    }
}

extern "C" void kernel_launch(void* const* d_in, const int* in_sizes, int n_in,
                              void* d_out, int out_size) {
    const float* E = (const float*)d_in[0];   // emissions   [B, C, L] f32
    const float* T = (const float*)d_in[1];   // transitions [L, L, C, C] f32
    float* M = (float*)d_out;                 // messages    [B, C, L] f32

    dim3 grid(64, 8);                         // 64 subtrees x 8 batch-groups
    k_all<<<grid, 256>>>(E, T, M);
}

// round 7
// speedup vs baseline: 1.0423x; 1.0423x over previous
#include <cuda_runtime.h>

// Tree DP on deterministic 4-ary heap: L=4096, B=64, C=2.
// msg[b,cs,k] = lse_{cj}( E[b,cj,j] + msg[b,cj,j] + T[k,j,cs,cj] ), j=(k-1)>>2.
//
// Warp = (subtree r in [21,85), batch b). Grid (64 x 8), 256 thr.
// The 87 T-float4s a block needs (3 path edges + 4 L3 + 16 L4 + 64 L5 lines,
// all in distinct 128B lines) are staged into smem ONCE per block by threads
// 0..86, instead of每 warp issuing ~87 scattered wavefronts itself (8x dedup).
// E loads are per-batch (intrinsic) and issued before the single barrier so
// they overlap the T DRAM wave. Parent values propagate via shfl, no smem DP.

#define LN  4096
#define CLN 8192

__device__ __forceinline__ float lse2(float a, float b) {
    float mx = fmaxf(a, b);
    float mn = fminf(a, b);
    return mx + __logf(1.0f + __expf(mn - mx));
}

__global__ void __launch_bounds__(256, 1)
k_all(const float* __restrict__ E, const float* __restrict__ T, float* __restrict__ M)
{
    __shared__ float4 sT[87];   // [0..2]=path A,B,C  [3..6]=L3  [7..22]=L4  [23..86]=L5

    const int tid  = threadIdx.x;
    const int lane = tid & 31;
    const int w    = tid >> 5;
    const int r    = 21 + blockIdx.x;            // subtree root, [21,85)
    const int b    = blockIdx.y * 8 + w;         // this warp's batch

    const int p2 = (r - 1) >> 2;
    const int p1 = (p2 - 1) >> 2;

    const float4* __restrict__ T4 = (const float4*)T;
    const float*  __restrict__ Eb = E + b * CLN;

    // -------- cooperative T stage: one load per distinct line --------
    if (tid < 87) {
        int idx;
        if      (tid == 0) idx = p1 * LN + 0;
        else if (tid == 1) idx = p2 * LN + p1;
        else if (tid == 2) idx = r  * LN + p2;
        else if (tid < 7)  { int k = 4 * r + 1 + (tid - 3);  idx = k * LN + r; }
        else if (tid < 23) { int k = 16 * r + 5 + (tid - 7); idx = k * LN + ((k - 1) >> 2); }
        else {
            int k = 64 * r + 21 + (tid - 23);
            idx = (k < LN) ? (k * LN + ((k - 1) >> 2)) : -1;
        }
        if (idx >= 0) sT[tid] = __ldg(T4 + idx);
    }

    // -------- per-warp E prefetch (overlaps the T wave) --------
    float eR0 = Eb[0],  eR1 = Eb[LN];
    float e10 = Eb[p1], e11 = Eb[LN + p1];
    float e20 = Eb[p2], e21 = Eb[LN + p2];
    float er0 = Eb[r],  er1 = Eb[LN + r];

    const int n3 = lane & 3;
    const int k3 = 4 * r + 1 + n3;
    float e30 = Eb[k3], e31 = Eb[LN + k3];

    const int n4 = lane & 15;
    const int k4 = 16 * r + 5 + n4;
    float e40 = Eb[k4], e41 = Eb[LN + k4];

    const int k5a = 64 * r + 21 + lane;
    const int k5b = k5a + 32;
    const bool va = (k5a < LN), vb = (k5b < LN);

    // node 0 never receives a message -> zero it (output poisoned)
    if (blockIdx.x == 0 && lane < 2)
        M[b * CLN + lane * LN] = 0.0f;

    __syncthreads();

    // -------- read staged T (LDS, broadcast/conflict-free) --------
    const float4 tA  = sT[0];
    const float4 tB  = sT[1];
    const float4 tC  = sT[2];
    const float4 t3  = sT[3 + n3];
    const float4 t4  = sT[7 + n4];
    const float4 t5a = sT[23 + lane];          // garbage if !va, unused
    const float4 t5b = sT[55 + lane];          // garbage if !vb, unused

    // -------- path root -> p1 -> p2 -> r (all lanes, redundant) --------
    float m0 = lse2(eR0 + tA.x, eR1 + tA.y);
    float m1 = lse2(eR0 + tA.z, eR1 + tA.w);
    if (lane == 0) { M[b * CLN + p1] = m0;  M[b * CLN + LN + p1] = m1; }
    float l0 = e10 + m0, l1 = e11 + m1;

    m0 = lse2(l0 + tB.x, l1 + tB.y);
    m1 = lse2(l0 + tB.z, l1 + tB.w);
    if (lane == 0) { M[b * CLN + p2] = m0;  M[b * CLN + LN + p2] = m1; }
    l0 = e20 + m0;  l1 = e21 + m1;

    m0 = lse2(l0 + tC.x, l1 + tC.y);
    m1 = lse2(l0 + tC.z, l1 + tC.w);
    if (lane == 0) { M[b * CLN + r] = m0;   M[b * CLN + LN + r] = m1; }
    const float lr0 = er0 + m0, lr1 = er1 + m1;     // local(r), every lane

    // -------- level 3 (4 nodes; lanes hold node lane&3) --------
    float m30 = lse2(lr0 + t3.x, lr1 + t3.y);
    float m31 = lse2(lr0 + t3.z, lr1 + t3.w);
    if (lane < 4) { M[b * CLN + k3] = m30;  M[b * CLN + LN + k3] = m31; }
    float l30 = e30 + m30, l31 = e31 + m31;

    // -------- level 4 (16 nodes; lanes hold node lane&15) --------
    float p40 = __shfl_sync(0xffffffffu, l30, n4 >> 2);
    float p41 = __shfl_sync(0xffffffffu, l31, n4 >> 2);
    float m40 = lse2(p40 + t4.x, p41 + t4.y);
    float m41 = lse2(p40 + t4.z, p41 + t4.w);
    if (lane < 16) { M[b * CLN + k4] = m40;  M[b * CLN + LN + k4] = m41; }
    float l40 = e40 + m40, l41 = e41 + m41;

    // -------- level 5 (up to 64 leaves) --------
    float a0 = __shfl_sync(0xffffffffu, l40, lane >> 2);          // parents 0..7
    float a1 = __shfl_sync(0xffffffffu, l41, lane >> 2);
    float c0 = __shfl_sync(0xffffffffu, l40, 8 + (lane >> 2));    // parents 8..15
    float c1 = __shfl_sync(0xffffffffu, l41, 8 + (lane >> 2));
    if (va) {
        float x0 = lse2(a0 + t5a.x, a1 + t5a.y);
        float x1 = lse2(a0 + t5a.z, a1 + t5a.w);
        M[b * CLN + k5a] = x0;  M[b * CLN + LN + k5a] = x1;       // coalesced
    }
    if (vb) {
        float y0 = lse2(c0 + t5b.x, c1 + t5b.y);
        float y1 = lse2(c0 + t5b.z, c1 + t5b.w);
        M[b * CLN + k5b] = y0;  M[b * CLN + LN + k5b] = y1;
    }
}

extern "C" void kernel_launch(void* const* d_in, const int* in_sizes, int n_in,
                              void* d_out, int out_size) {
    const float* E = (const float*)d_in[0];   // emissions   [B, C, L] f32
    const float* T = (const float*)d_in[1];   // transitions [L, L, C, C] f32
    float* M = (float*)d_out;                 // messages    [B, C, L] f32

    dim3 grid(64, 8);
    k_all<<<grid, 256>>>(E, T, M);
}